// round 2
// baseline (speedup 1.0000x reference)
#include <cuda_runtime.h>
#include <math_constants.h>

#define BB 32
#define LL 2048
#define DD 1024

// Scratch: __device__ globals (no allocation allowed in kernel_launch).
__device__ float g_f1[BB * LL];
__device__ float g_f2[BB * LL];
__device__ float g_a [BB * LL];

// ---------------------------------------------------------------------------
// Kernel 1: f1[b,l] = dot(emb[b,l,:], w1), f2 likewise. One warp per row.
// ---------------------------------------------------------------------------
__global__ __launch_bounds__(256) void k_proj(const float* __restrict__ emb,
                                              const float* __restrict__ w1,
                                              const float* __restrict__ w2) {
    __shared__ float4 sw1[DD / 4];
    __shared__ float4 sw2[DD / 4];
    int t = threadIdx.x;
    // 256 threads load exactly DD/4 = 256 float4s each for w1 and w2.
    sw1[t] = ((const float4*)w1)[t];
    sw2[t] = ((const float4*)w2)[t];
    __syncthreads();

    int warp = t >> 5;
    int lane = t & 31;
    int row  = blockIdx.x * 8 + warp;   // row in [0, BB*LL)

    const float4* e = (const float4*)(emb + (size_t)row * DD);
    // Two independent accumulator pairs -> shorter FFMA dependency chains,
    // more memory-level parallelism across the 8 outstanding loads.
    float a1 = 0.f, a2 = 0.f, b1 = 0.f, b2 = 0.f;
#pragma unroll
    for (int k = 0; k < 8; k += 2) {
        int i0 = k * 32 + lane;
        int i1 = (k + 1) * 32 + lane;
        float4 e0 = e[i0];
        float4 e1 = e[i1];
        float4 u1 = sw1[i0], u2 = sw2[i0];
        float4 v1 = sw1[i1], v2 = sw2[i1];
        a1 += e0.x * u1.x + e0.y * u1.y + e0.z * u1.z + e0.w * u1.w;
        a2 += e0.x * u2.x + e0.y * u2.y + e0.z * u2.z + e0.w * u2.w;
        b1 += e1.x * v1.x + e1.y * v1.y + e1.z * v1.z + e1.w * v1.w;
        b2 += e1.x * v2.x + e1.y * v2.y + e1.z * v2.z + e1.w * v2.w;
    }
    a1 += b1;
    a2 += b2;
#pragma unroll
    for (int o = 16; o; o >>= 1) {
        a1 += __shfl_xor_sync(0xffffffffu, a1, o);
        a2 += __shfl_xor_sync(0xffffffffu, a2, o);
    }
    if (lane == 0) {
        g_f1[row] = a1;
        g_f2[row] = a2;
    }
}

// ---------------------------------------------------------------------------
// Kernel 2: per-batch top-2 of f2, then softmax over g = f1 + offdiag + bias.
// One block (256 threads) per batch. All reductions over L=2048 scalars.
// ---------------------------------------------------------------------------
__global__ __launch_bounds__(256) void k_softmax(const float* __restrict__ bias) {
    int b = blockIdx.x;
    int t = threadIdx.x;
    const float* f1 = g_f1 + b * LL;
    const float* f2 = g_f2 + b * LL;

    __shared__ float sval[256];
    __shared__ int   sidx[256];

    // --- argmax of f2 (tie-break: lowest index, matching jax.lax.top_k) ---
    float mv = -CUDART_INF_F;
    int   mi = 0x7fffffff;
    for (int l = t; l < LL; l += 256) {
        float v = f2[l];
        if (v > mv || (v == mv && l < mi)) { mv = v; mi = l; }
    }
    sval[t] = mv; sidx[t] = mi;
    __syncthreads();
    for (int s = 128; s; s >>= 1) {
        if (t < s) {
            if (sval[t + s] > sval[t] ||
                (sval[t + s] == sval[t] && sidx[t + s] < sidx[t])) {
                sval[t] = sval[t + s];
                sidx[t] = sidx[t + s];
            }
        }
        __syncthreads();
    }
    float v0 = sval[0];
    int   i0 = sidx[0];
    __syncthreads();

    // --- second max: max over l != i0 ---
    float m2 = -CUDART_INF_F;
    for (int l = t; l < LL; l += 256)
        if (l != i0) m2 = fmaxf(m2, f2[l]);
    sval[t] = m2;
    __syncthreads();
    for (int s = 128; s; s >>= 1) {
        if (t < s) sval[t] = fmaxf(sval[t], sval[t + s]);
        __syncthreads();
    }
    float v1 = sval[0];
    __syncthreads();

    float bv = bias[0];

    // --- max of g ---
    float gmax = -CUDART_INF_F;
    for (int l = t; l < LL; l += 256) {
        float g = f1[l] + ((l == i0) ? v1 : v0) + bv;
        gmax = fmaxf(gmax, g);
    }
    sval[t] = gmax;
    __syncthreads();
    for (int s = 128; s; s >>= 1) {
        if (t < s) sval[t] = fmaxf(sval[t], sval[t + s]);
        __syncthreads();
    }
    gmax = sval[0];
    __syncthreads();

    // --- sum of exp ---
    float ssum = 0.f;
    for (int l = t; l < LL; l += 256) {
        float g = f1[l] + ((l == i0) ? v1 : v0) + bv;
        ssum += expf(g - gmax);
    }
    sval[t] = ssum;
    __syncthreads();
    for (int s = 128; s; s >>= 1) {
        if (t < s) sval[t] += sval[t + s];
        __syncthreads();
    }
    float invZ = 1.f / sval[0];

    // --- write normalized weights ---
    for (int l = t; l < LL; l += 256) {
        float g = f1[l] + ((l == i0) ? v1 : v0) + bv;
        g_a[b * LL + l] = expf(g - gmax) * invZ;
    }
}

// ---------------------------------------------------------------------------
// Kernel 3: v[b,d] = sum_l a[b,l] * emb[b,l,d].
// Grid (chunk, batch); each thread owns one float4 column slice across
// ROWS_PER_CHUNK rows, then atomically accumulates into d_out.
// ---------------------------------------------------------------------------
#define CHUNKS 16
#define ROWS_PER_CHUNK (LL / CHUNKS)   // 128

__global__ __launch_bounds__(256) void k_wsum(const float* __restrict__ emb,
                                              float* __restrict__ out) {
    int b     = blockIdx.y;
    int chunk = blockIdx.x;
    int t     = threadIdx.x;

    const float*  aw = g_a + b * LL + chunk * ROWS_PER_CHUNK;
    const float4* e  = (const float4*)(emb +
                        ((size_t)b * LL + (size_t)chunk * ROWS_PER_CHUNK) * DD) + t;

    float4 acc = make_float4(0.f, 0.f, 0.f, 0.f);
#pragma unroll
    for (int r = 0; r < ROWS_PER_CHUNK; r += 4) {
        // Front-batch the weight loads, then the 4 independent 16B row loads.
        float w0 = aw[r + 0], w1 = aw[r + 1], w2 = aw[r + 2], w3 = aw[r + 3];
        float4 e0 = e[(size_t)(r + 0) * (DD / 4)];
        float4 e1 = e[(size_t)(r + 1) * (DD / 4)];
        float4 e2 = e[(size_t)(r + 2) * (DD / 4)];
        float4 e3 = e[(size_t)(r + 3) * (DD / 4)];
        acc.x += w0 * e0.x; acc.y += w0 * e0.y; acc.z += w0 * e0.z; acc.w += w0 * e0.w;
        acc.x += w1 * e1.x; acc.y += w1 * e1.y; acc.z += w1 * e1.z; acc.w += w1 * e1.w;
        acc.x += w2 * e2.x; acc.y += w2 * e2.y; acc.z += w2 * e2.z; acc.w += w2 * e2.w;
        acc.x += w3 * e3.x; acc.y += w3 * e3.y; acc.z += w3 * e3.z; acc.w += w3 * e3.w;
    }
    float* o = out + b * DD + t * 4;
    atomicAdd(o + 0, acc.x);
    atomicAdd(o + 1, acc.y);
    atomicAdd(o + 2, acc.z);
    atomicAdd(o + 3, acc.w);
}

// ---------------------------------------------------------------------------
// Launch: memset(out) -> proj -> softmax -> weighted sum. All graph-capturable.
// ---------------------------------------------------------------------------
extern "C" void kernel_launch(void* const* d_in, const int* in_sizes, int n_in,
                              void* d_out, int out_size) {
    const float* emb  = (const float*)d_in[0];
    const float* w1   = (const float*)d_in[1];
    const float* w2   = (const float*)d_in[2];
    const float* bias = (const float*)d_in[3];
    float* out = (float*)d_out;

    cudaMemsetAsync(out, 0, (size_t)BB * DD * sizeof(float));

    k_proj<<<(BB * LL) / 8, 256>>>(emb, w1, w2);
    k_softmax<<<BB, 256>>>(bias);

    dim3 grid(CHUNKS, BB);
    k_wsum<<<grid, 256>>>(emb, out);
}